// round 7
// baseline (speedup 1.0000x reference)
#include <cuda_runtime.h>
#include <cuda_fp16.h>
#include <cstdint>

// Problem constants (fixed by setup_inputs)
#define BATCH 128
#define IC    2048
#define OC    32
#define OD    16
#define ROW   512          // OC*OD floats per (b,i) row
#define THREADS 256
#define WPB   8            // warps per block
#define BPB   8            // blocks per batch
#define IPW   32           // IC rows per warp
#define NPAIR 16           // row pairs per warp
#define DROWS 8            // smem staging ring depth (rows) = 4 pair slots

typedef unsigned long long u64;

#define LOG2E_F 1.4426950408889634f

// Scratch (device globals: allocation-free per harness rules)
__device__ __align__(16) __half g_u16[(size_t)BATCH * IC * ROW];   // 268 MB fp16 copy of u
__device__ __align__(16) float  g_part[(size_t)BATCH * BPB * ROW]; // 2 MB block partials
__device__ __align__(16) float  g_vsum[(size_t)BATCH * ROW];       // 256 KB running v sum
__device__ int g_cnt[BATCH];                                       // zero-init; self-resetting

__device__ __forceinline__ void cp_async16(unsigned saddr, const void* gptr) {
    asm volatile("cp.async.cg.shared.global [%0], [%1], 16;\n"
                 :: "r"(saddr), "l"(gptr) : "memory");
}
// Packed f32x2 helpers (sm_103a FFMA2 path)
__device__ __forceinline__ u64 pack_f2(float lo, float hi) {
    u64 r; asm("mov.b64 %0, {%1, %2};" : "=l"(r) : "f"(lo), "f"(hi)); return r;
}
__device__ __forceinline__ void unpack_f2(u64 v, float& lo, float& hi) {
    asm("mov.b64 {%0, %1}, %2;" : "=f"(lo), "=f"(hi) : "l"(v));
}
__device__ __forceinline__ void ffma2(u64& d, u64 a, u64 b) {
    asm("fma.rn.f32x2 %0, %1, %2, %0;" : "+l"(d) : "l"(a), "l"(b));
}
__device__ __forceinline__ float ex2a(float x) {
    float y; asm("ex2.approx.f32 %0, %1;" : "=f"(y) : "f"(x)); return y;
}
__device__ __forceinline__ float rcpa(float x) {
    float y; asm("rcp.approx.f32 %0, %1;" : "=f"(y) : "f"(x)); return y;
}

// Cross-block reduction + squash, after warp partials are in sred.
// mode 0: vsum = v; mode 1: vsum += v; mode 2: out = v.
__device__ __forceinline__ void block_tail_reduce(float (*sred)[ROW], int b, int chunk,
                                                  int mode, float* __restrict__ out)
{
    __shared__ bool amLast;
    const int t = threadIdx.x;
    float r0 = 0.f, r1 = 0.f;
    #pragma unroll
    for (int w = 0; w < WPB; ++w) { r0 += sred[w][t]; r1 += sred[w][t + 256]; }
    float* bp = g_part + ((size_t)b * BPB + chunk) * ROW;
    bp[t] = r0; bp[t + 256] = r1;

    __threadfence();
    __syncthreads();
    if (t == 0) {
        int old = atomicAdd(&g_cnt[b], 1);
        amLast = (old == BPB - 1);
        if (amLast) g_cnt[b] = 0;      // replay-safe reset
    }
    __syncthreads();
    if (!amLast) return;
    __threadfence();                   // acquire: see all blocks' partials

    const float* pb = g_part + (size_t)b * BPB * ROW;
    float s0 = 0.f, s1 = 0.f;
    #pragma unroll
    for (int c = 0; c < BPB; ++c) {    // fixed order -> deterministic
        s0 += pb[(size_t)c * ROW + t];
        s1 += pb[(size_t)c * ROW + t + 256];
    }

    // squash: ||s||^2 over the 16 d-lanes of each o
    const unsigned FULL = 0xffffffffu;
    float q0 = s0 * s0, q1 = s1 * s1;
    #pragma unroll
    for (int m = 1; m < 16; m <<= 1) {
        q0 += __shfl_xor_sync(FULL, q0, m);
        q1 += __shfl_xor_sync(FULL, q1, m);
    }
    float v0 = s0 * sqrtf(q0) / (1.f + q0);
    float v1 = s1 * sqrtf(q1) / (1.f + q1);

    float* vs = g_vsum + (size_t)b * ROW;
    if (mode == 0)      { vs[t] = v0;            vs[t + 256] = v1; }
    else if (mode == 1) { vs[t] += v0;           vs[t + 256] += v1; }
    else                { out[(size_t)b * ROW + t] = v0;
                          out[(size_t)b * ROW + t + 256] = v1; }
}

// Init pass: c = softmax(b_in), s = sum_i c*u; emits fp16 copy of u.
// HBM-bound (804 MB) at ~7.8 TB/s already — unchanged.
__global__ __launch_bounds__(THREADS)
void rba_init(const float* __restrict__ u, const float* __restrict__ bin)
{
    __shared__ float sred[WPB][ROW];
    const int b     = blockIdx.x >> 3;
    const int chunk = blockIdx.x & 7;
    const int warp  = threadIdx.x >> 5;
    const int lane  = threadIdx.x & 31;
    const int g     = lane >> 2;
    const int wc    = chunk * WPB + warp;
    const unsigned FULL = 0xffffffffu;

    float4 acc[4];
    #pragma unroll
    for (int j = 0; j < 4; ++j) acc[j] = make_float4(0.f, 0.f, 0.f, 0.f);

    const size_t ubase = ((size_t)b * IC + (size_t)wc * IPW) * ROW;

    for (int ii = 0; ii < IPW; ++ii) {
        const int i = wc * IPW + ii;
        const float4* up = reinterpret_cast<const float4*>(u + ubase + (size_t)ii * ROW);
        __half* dst = g_u16 + ubase + (size_t)ii * ROW;

        float4 u4[4];
        #pragma unroll
        for (int j = 0; j < 4; ++j) u4[j] = up[j * 32 + lane];   // coalesced 2KB/row

        #pragma unroll
        for (int j = 0; j < 4; ++j) {
            union { uint2 raw; __half2 h[2]; } pk;
            pk.h[0] = __floats2half2_rn(u4[j].x, u4[j].y);
            pk.h[1] = __floats2half2_rn(u4[j].z, u4[j].w);
            *reinterpret_cast<uint2*>(dst + j * 128 + lane * 4) = pk.raw;
        }

        float bv = bin[(size_t)i * OC + lane];
        float logit[4];
        #pragma unroll
        for (int j = 0; j < 4; ++j) logit[j] = __shfl_sync(FULL, bv, j * 8 + g);

        float e[4], Z = 0.f;
        #pragma unroll
        for (int j = 0; j < 4; ++j) { e[j] = __expf(logit[j]); Z += e[j]; }
        Z += __shfl_xor_sync(FULL, Z, 4);
        Z += __shfl_xor_sync(FULL, Z, 8);
        Z += __shfl_xor_sync(FULL, Z, 16);
        float rZ = __frcp_rn(Z);
        #pragma unroll
        for (int j = 0; j < 4; ++j) {
            float c = e[j] * rZ;
            acc[j].x += c * u4[j].x; acc[j].y += c * u4[j].y;
            acc[j].z += c * u4[j].z; acc[j].w += c * u4[j].w;
        }
    }

    #pragma unroll
    for (int j = 0; j < 4; ++j)
        *reinterpret_cast<float4*>(&sred[warp][j * 128 + lane * 4]) = acc[j];
    __syncthreads();
    block_tail_reduce(sred, b, chunk, /*mode=*/0, nullptr);
}

// Agreement pass: logits = bin + dot(u, vsum); c = softmax; s = sum_i c*u.
// fp16 u via cp.async 8-row (4 pair-slot) smem ring; TWO independent rows per
// loop iteration (2x ILP per warp); base-2 exponentials with pre-scaled v/bin;
// packed f32x2 FMA; sred aliases the stage buffer; 3 blocks/SM.
template<int MODE>
__global__ __launch_bounds__(THREADS, 3)
void rba_iter(const float* __restrict__ bin, float* __restrict__ out)
{
    __shared__ __align__(16) char smem_raw[WPB * DROWS * ROW * 2];   // 64 KB
    __half (*stage)[DROWS][ROW] = reinterpret_cast<__half(*)[DROWS][ROW]>(smem_raw);
    float  (*sred)[ROW]         = reinterpret_cast<float(*)[ROW]>(smem_raw);

    const int b     = blockIdx.x >> 3;
    const int chunk = blockIdx.x & 7;
    const int warp  = threadIdx.x >> 5;
    const int lane  = threadIdx.x & 31;
    const int wc    = chunk * WPB + warp;
    const unsigned FULL = 0xffffffffu;

    // vsum packed & pre-scaled by log2(e): slot A floats [8*lane,+8), slot B +256
    u64 vpA[4], vpB[4];
    {
        const float* vb = g_vsum + (size_t)b * ROW + lane * 8;
        float4 a0 = *reinterpret_cast<const float4*>(vb);
        float4 a1 = *reinterpret_cast<const float4*>(vb + 4);
        float4 b0 = *reinterpret_cast<const float4*>(vb + 256);
        float4 b1 = *reinterpret_cast<const float4*>(vb + 260);
        vpA[0] = pack_f2(a0.x*LOG2E_F, a0.y*LOG2E_F); vpA[1] = pack_f2(a0.z*LOG2E_F, a0.w*LOG2E_F);
        vpA[2] = pack_f2(a1.x*LOG2E_F, a1.y*LOG2E_F); vpA[3] = pack_f2(a1.z*LOG2E_F, a1.w*LOG2E_F);
        vpB[0] = pack_f2(b0.x*LOG2E_F, b0.y*LOG2E_F); vpB[1] = pack_f2(b0.z*LOG2E_F, b0.w*LOG2E_F);
        vpB[2] = pack_f2(b1.x*LOG2E_F, b1.y*LOG2E_F); vpB[3] = pack_f2(b1.z*LOG2E_F, b1.w*LOG2E_F);
    }

    u64 accA[4], accB[4];
    #pragma unroll
    for (int k = 0; k < 4; ++k) { accA[k] = 0ull; accB[k] = 0ull; }

    const __half* up = g_u16 + ((size_t)b * IC + (size_t)wc * IPW) * ROW;
    const int loff = lane * 8;                 // halves
    const int src0 = lane >> 1;                // shfl source for bin broadcast

    const unsigned sbase =
        (unsigned)__cvta_generic_to_shared(&stage[warp][0][0]) + loff * 2;

    // prologue: pairs 0..2 in flight (rows 0..5), one commit group per pair
    #pragma unroll
    for (int p = 0; p < 3; ++p) {
        const __half* g0 = up + (size_t)(2 * p) * ROW + loff;
        const unsigned sa = sbase + (2 * p) * (ROW * 2);
        cp_async16(sa,        g0);
        cp_async16(sa + 512,  g0 + 256);
        cp_async16(sa + 1024, g0 + ROW);
        cp_async16(sa + 1536, g0 + ROW + 256);
        asm volatile("cp.async.commit_group;\n" ::: "memory");
    }

    #pragma unroll 4
    for (int t = 0; t < NPAIR; ++t) {
        // early LDGs of the logit prior (L2-resident), pre-scaled to base-2
        const int i0 = wc * IPW + 2 * t;
        float bv0 = bin[(size_t)i0 * OC + lane] * LOG2E_F;
        float bv1 = bin[(size_t)(i0 + 1) * OC + lane] * LOG2E_F;

        const int pf = t + 3;
        if (pf < NPAIR) {
            const __half* g0 = up + (size_t)(2 * pf) * ROW + loff;
            const unsigned sa = sbase + ((2 * pf) & (DROWS - 1)) * (ROW * 2);
            cp_async16(sa,        g0);
            cp_async16(sa + 512,  g0 + 256);
            cp_async16(sa + 1024, g0 + ROW);
            cp_async16(sa + 1536, g0 + ROW + 256);
        }
        asm volatile("cp.async.commit_group;\n" ::: "memory");
        asm volatile("cp.async.wait_group 3;\n" ::: "memory");   // pair t ready

        const int s = (2 * t) & (DROWS - 1);
        uint4 rA0 = *reinterpret_cast<const uint4*>(&stage[warp][s][loff]);
        uint4 rB0 = *reinterpret_cast<const uint4*>(&stage[warp][s][256 + loff]);
        uint4 rA1 = *reinterpret_cast<const uint4*>(&stage[warp][s + 1][loff]);
        uint4 rB1 = *reinterpret_cast<const uint4*>(&stage[warp][s + 1][256 + loff]);

        // unpack both rows to packed f32x2
        u64 uPA0[4], uPB0[4], uPA1[4], uPB1[4];
        {
            const __half2* hA0 = reinterpret_cast<const __half2*>(&rA0);
            const __half2* hB0 = reinterpret_cast<const __half2*>(&rB0);
            const __half2* hA1 = reinterpret_cast<const __half2*>(&rA1);
            const __half2* hB1 = reinterpret_cast<const __half2*>(&rB1);
            #pragma unroll
            for (int k = 0; k < 4; ++k) {
                float2 f;
                f = __half22float2(hA0[k]); uPA0[k] = pack_f2(f.x, f.y);
                f = __half22float2(hB0[k]); uPB0[k] = pack_f2(f.x, f.y);
                f = __half22float2(hA1[k]); uPA1[k] = pack_f2(f.x, f.y);
                f = __half22float2(hB1[k]); uPB1[k] = pack_f2(f.x, f.y);
            }
        }

        // packed dots (pre-scaled by log2e via v)
        u64 dA0 = 0ull, dB0 = 0ull, dA1 = 0ull, dB1 = 0ull;
        #pragma unroll
        for (int k = 0; k < 4; ++k) {
            ffma2(dA0, uPA0[k], vpA[k]); ffma2(dB0, uPB0[k], vpB[k]);
            ffma2(dA1, uPA1[k], vpA[k]); ffma2(dB1, uPB1[k], vpB[k]);
        }
        float xl, xh;
        unpack_f2(dA0, xl, xh); float pA0 = xl + xh;
        unpack_f2(dB0, xl, xh); float pB0 = xl + xh;
        unpack_f2(dA1, xl, xh); float pA1 = xl + xh;
        unpack_f2(dB1, xl, xh); float pB1 = xl + xh;
        pA0 += __shfl_xor_sync(FULL, pA0, 1);
        pB0 += __shfl_xor_sync(FULL, pB0, 1);
        pA1 += __shfl_xor_sync(FULL, pA1, 1);
        pB1 += __shfl_xor_sync(FULL, pB1, 1);

        float blA0 = __shfl_sync(FULL, bv0, src0);
        float blB0 = __shfl_sync(FULL, bv0, 16 + src0);
        float blA1 = __shfl_sync(FULL, bv1, src0);
        float blB1 = __shfl_sync(FULL, bv1, 16 + src0);

        float eA0 = ex2a(blA0 + pA0), eB0 = ex2a(blB0 + pB0);
        float eA1 = ex2a(blA1 + pA1), eB1 = ex2a(blB1 + pB1);

        float Z0 = eA0 + eB0, Z1 = eA1 + eB1;
        // xor{2,4,8,16} sums each of the 32 output caps exactly once
        Z0 += __shfl_xor_sync(FULL, Z0, 2);  Z1 += __shfl_xor_sync(FULL, Z1, 2);
        Z0 += __shfl_xor_sync(FULL, Z0, 4);  Z1 += __shfl_xor_sync(FULL, Z1, 4);
        Z0 += __shfl_xor_sync(FULL, Z0, 8);  Z1 += __shfl_xor_sync(FULL, Z1, 8);
        Z0 += __shfl_xor_sync(FULL, Z0, 16); Z1 += __shfl_xor_sync(FULL, Z1, 16);
        float rZ0 = rcpa(Z0), rZ1 = rcpa(Z1);

        u64 cA0 = pack_f2(eA0 * rZ0, eA0 * rZ0);
        u64 cB0 = pack_f2(eB0 * rZ0, eB0 * rZ0);
        u64 cA1 = pack_f2(eA1 * rZ1, eA1 * rZ1);
        u64 cB1 = pack_f2(eB1 * rZ1, eB1 * rZ1);

        #pragma unroll
        for (int k = 0; k < 4; ++k) {
            ffma2(accA[k], cA0, uPA0[k]); ffma2(accB[k], cB0, uPB0[k]);
            ffma2(accA[k], cA1, uPA1[k]); ffma2(accB[k], cB1, uPB1[k]);
        }
    }

    asm volatile("cp.async.wait_group 0;\n" ::: "memory");
    __syncthreads();                       // stage dead; safe to alias as sred

    float aa[8], bb[8];
    #pragma unroll
    for (int k = 0; k < 4; ++k) {
        unpack_f2(accA[k], aa[2*k], aa[2*k+1]);
        unpack_f2(accB[k], bb[2*k], bb[2*k+1]);
    }
    float* w0 = &sred[warp][lane * 8];
    *reinterpret_cast<float4*>(w0)       = make_float4(aa[0], aa[1], aa[2], aa[3]);
    *reinterpret_cast<float4*>(w0 + 4)   = make_float4(aa[4], aa[5], aa[6], aa[7]);
    *reinterpret_cast<float4*>(w0 + 256) = make_float4(bb[0], bb[1], bb[2], bb[3]);
    *reinterpret_cast<float4*>(w0 + 260) = make_float4(bb[4], bb[5], bb[6], bb[7]);
    __syncthreads();
    block_tail_reduce(sred, b, chunk, MODE, out);
}

extern "C" void kernel_launch(void* const* d_in, const int* in_sizes, int n_in,
                              void* d_out, int out_size)
{
    const float* u   = (const float*)d_in[0];  // [128,2048,32,16] f32
    const float* bin = (const float*)d_in[1];  // [2048,32] f32
    float* out = (float*)d_out;                // [128,32,16] f32

    const dim3 grid(BATCH * BPB);

    // v0 = squash(sum c0*u), c0 = softmax(bin); emit fp16 u; vsum = v0
    rba_init<<<grid, THREADS>>>(u, bin);
    // iter1: logits = bin + u.v0          ; vsum += v1
    rba_iter<1><<<grid, THREADS>>>(bin, out);
    // iter2: logits = bin + u.(v0+v1)     ; vsum += v2
    rba_iter<1><<<grid, THREADS>>>(bin, out);
    // iter3: logits = bin + u.(v0+v1+v2)  ; out = v3
    rba_iter<2><<<grid, THREADS>>>(bin, out);

    (void)in_sizes; (void)n_in; (void)out_size;
}